// round 15
// baseline (speedup 1.0000x reference)
#include <cuda_runtime.h>
#include <cuda_fp16.h>
#include <cstdint>

#define B_ 16
#define T_ 1024
#define D_ 1024
#define M_ (B_ * T_)            // 16384
#define NELEM (B_ * T_ * D_)    // 16777216

#define WSCALE 16.0f
#define WUNSCALE 0.0625f

#define SEGLEN 128
#define NSEG (T_ / SEGLEN)      // 8
#define WARMUP 192

// Work queue phase ranges (single atomic counter)
#define NW 8                    // W-prep items (128 rows each)
#define NX 512                  // X-prep items (32 rows each)
#define NG 1024                 // GEMM tiles (128x128)
#define NL 512                  // lif items (batch, seg, chain-block)
#define QW0 0
#define QX0 (QW0 + NW)          // 8
#define QG0 (QX0 + NX)          // 520
#define QL0 (QG0 + NG)          // 1544
#define QEND (QL0 + NL)         // 2056

#define GRID_PERSIST 296        // 2 CTAs/SM x 148

// ---------------------------------------------------------------------------
// Scratch (static device globals)
// ---------------------------------------------------------------------------
__device__ __half g_xh[NELEM];
__device__ __half g_xl[NELEM];
__device__ __half g_wh[D_ * D_];
__device__ __half g_wl[D_ * D_];
__device__ float g_ic[NELEM];
__device__ int g_q;             // unified work queue head
__device__ int g_wdone;         // W-prep items done (target 8)
__device__ int g_pdone[128];    // per-m-tile X-prep items done (target 4)
__device__ int g_done[B_];      // per-batch GEMM tiles done (target 64)

// ---------------------------------------------------------------------------
// Helpers
// ---------------------------------------------------------------------------
__device__ __forceinline__ uint32_t h2_as_u32(__half2 v) {
    uint32_t r;
    memcpy(&r, &v, 4);
    return r;
}
__device__ __forceinline__ uint32_t smem_u32(const void* p) {
    uint32_t a;
    asm("{ .reg .u64 t; cvta.to.shared.u64 t, %1; cvt.u32.u64 %0, t; }" : "=r"(a) : "l"(p));
    return a;
}
__device__ __forceinline__ void cpa16(uint32_t dst, const void* src) {
    asm volatile("cp.async.cg.shared.global [%0], [%1], 16;" :: "r"(dst), "l"(src));
}
#define CP_COMMIT() asm volatile("cp.async.commit_group;" ::: "memory")
#define CP_WAIT(n)  asm volatile("cp.async.wait_group %0;" :: "n"(n) : "memory")

__device__ __forceinline__ void ldsm_x4(uint32_t& r0, uint32_t& r1, uint32_t& r2,
                                        uint32_t& r3, uint32_t addr) {
    asm volatile("ldmatrix.sync.aligned.m8n8.x4.shared.b16 {%0,%1,%2,%3}, [%4];"
                 : "=r"(r0), "=r"(r1), "=r"(r2), "=r"(r3) : "r"(addr));
}
__device__ __forceinline__ void ldsm_x2(uint32_t& r0, uint32_t& r1, uint32_t addr) {
    asm volatile("ldmatrix.sync.aligned.m8n8.x2.shared.b16 {%0,%1}, [%2];"
                 : "=r"(r0), "=r"(r1) : "r"(addr));
}
__device__ __forceinline__ void mma16816(float* c, uint32_t a0, uint32_t a1,
                                         uint32_t a2, uint32_t a3,
                                         uint32_t b0, uint32_t b1) {
    asm volatile(
        "mma.sync.aligned.m16n8k16.row.col.f32.f16.f16.f32 "
        "{%0,%1,%2,%3}, {%4,%5,%6,%7}, {%8,%9}, {%0,%1,%2,%3};"
        : "+f"(c[0]), "+f"(c[1]), "+f"(c[2]), "+f"(c[3])
        : "r"(a0), "r"(a1), "r"(a2), "r"(a3), "r"(b0), "r"(b1));
}
__device__ __forceinline__ void split_h(float v, __half& hi, __half& lo) {
    __half h = __float2half_rn(v);
    lo = __float2half_rn(v - __half2float(h));
    hi = h;
}
__device__ __forceinline__ float lif_step(float mem, float icv, float nzv, bool& s) {
    float add = fmaf(nzv, 7.5e-4f, icv) + 1e-6f;
    mem = fmaf(0.95f, mem, add);
    s = (mem >= 0.15f);
    return s ? -0.05f : mem;
}

// ---------------------------------------------------------------------------
// Reset kernel: zero queue + flags (stream-ordered before mega)
// ---------------------------------------------------------------------------
__global__ void reset_kernel() {
    int t = threadIdx.x;
    if (t == 0) g_q = 0;
    if (t == 1) g_wdone = 0;
    if (t >= 2 && t < 2 + B_) g_done[t - 2] = 0;
    if (t >= 32 && t < 32 + 128) g_pdone[t - 32] = 0;
}

// ---------------------------------------------------------------------------
// Work item: W-prep (128 rows of W*16 -> fp16 limbs)
// ---------------------------------------------------------------------------
__device__ void w_item(int item, const float* __restrict__ w, int tid) {
    int base4 = item * (128 * D_ / 4);  // float4 index
    for (int t = 0; t < 128; t++) {
        int i = base4 + t * 256 + tid;
        float4 v = ((const float4*)w)[i];
        __half h0, h1, h2, h3, l0, l1, l2, l3;
        split_h(v.x * WSCALE, h0, l0); split_h(v.y * WSCALE, h1, l1);
        split_h(v.z * WSCALE, h2, l2); split_h(v.w * WSCALE, h3, l3);
        __half2 hv0 = __halves2half2(h0, h1), hv1 = __halves2half2(h2, h3);
        __half2 lv0 = __halves2half2(l0, l1), lv1 = __halves2half2(l2, l3);
        *(uint2*)&g_wh[i * 4] = make_uint2(h2_as_u32(hv0), h2_as_u32(hv1));
        *(uint2*)&g_wl[i * 4] = make_uint2(h2_as_u32(lv0), h2_as_u32(lv1));
    }
    __threadfence();
    __syncthreads();
    if (tid == 0) atomicAdd(&g_wdone, 1);
}

// ---------------------------------------------------------------------------
// Work item: X-prep (32 rows: tanh(0.5x) -> fp16 limbs)
// ---------------------------------------------------------------------------
__device__ void x_item(int item, const float* __restrict__ x, int tid) {
    int base4 = item * (32 * D_ / 4);
    for (int t = 0; t < 32; t++) {
        int i = base4 + t * 256 + tid;
        float4 v = ((const float4*)x)[i];
        float t0 = tanhf(0.5f * v.x), t1 = tanhf(0.5f * v.y);
        float t2 = tanhf(0.5f * v.z), t3 = tanhf(0.5f * v.w);
        __half h0, h1, h2, h3, l0, l1, l2, l3;
        split_h(t0, h0, l0); split_h(t1, h1, l1);
        split_h(t2, h2, l2); split_h(t3, h3, l3);
        __half2 hv0 = __halves2half2(h0, h1), hv1 = __halves2half2(h2, h3);
        __half2 lv0 = __halves2half2(l0, l1), lv1 = __halves2half2(l2, l3);
        *(uint2*)&g_xh[i * 4] = make_uint2(h2_as_u32(hv0), h2_as_u32(hv1));
        *(uint2*)&g_xl[i * 4] = make_uint2(h2_as_u32(lv0), h2_as_u32(lv1));
    }
    __threadfence();
    __syncthreads();
    if (tid == 0) atomicAdd(&g_pdone[item >> 2], 1);
}

// ---------------------------------------------------------------------------
// GEMM tile worker: 128x128 tile, BK=32, 8 warps, 2-stage cp.async,
// ldmatrix fragments, fp16 x3 limbs.
// ---------------------------------------------------------------------------
#define BKH 32
#define STR 40
#define ARR_B (128 * STR * 2)  // 10240
#define STAGE_B (4 * ARR_B)    // 40960
#define OAH 0
#define OAL ARR_B
#define OBH (2 * ARR_B)
#define OBL (3 * ARR_B)
#define NKT (D_ / BKH)         // 32

__device__ void gemm_tile(int tile, char* dsm, int tid) {
    const int y = tile >> 3;           // m-tile 0..127
    const int xw = tile & 7;           // n-tile 0..7
    const int m0 = y * 128;
    const int n0 = xw * 128;
    const int wid = tid >> 5;
    const int lid = tid & 31;
    const int grp = lid >> 2;
    const int tig = lid & 3;
    const int warp_m = (wid & 1) * 64;
    const int warp_n = (wid >> 1) * 32;
    const uint32_t sb = smem_u32(dsm);

    // wait for W fully prepped and this tile's A rows prepped
    if (tid == 0) {
        while (atomicAdd(&g_wdone, 0) < NW) __nanosleep(128);
        while (atomicAdd(&g_pdone[y], 0) < 4) __nanosleep(128);
    }
    __syncthreads();
    __threadfence();

    const int a_row = warp_m + (lid & 15);
    const int a_kof = (lid >> 4) * 8;
    const int b_row = warp_n + (lid & 7);
    const int b_kof = ((lid >> 3) & 1) * 8;

    float acc[4][4][4];
#pragma unroll
    for (int i = 0; i < 4; i++)
#pragma unroll
        for (int j = 0; j < 4; j++)
#pragma unroll
            for (int q = 0; q < 4; q++) acc[i][j][q] = 0.0f;

    auto load_stage = [&](int s, int kt) {
        const int k0 = kt * BKH;
        const uint32_t st = sb + s * STAGE_B;
#pragma unroll
        for (int t = 0; t < 2; t++) {
            int id = tid + t * 256;
            int r = id >> 2;
            int c = id & 3;
            uint32_t doff = (uint32_t)(r * 80 + c * 16);
            size_t ga = (size_t)(m0 + r) * D_ + k0 + c * 8;
            size_t gb = (size_t)(n0 + r) * D_ + k0 + c * 8;
            cpa16(st + OAH + doff, g_xh + ga);
            cpa16(st + OAL + doff, g_xl + ga);
            cpa16(st + OBH + doff, g_wh + gb);
            cpa16(st + OBL + doff, g_wl + gb);
        }
    };

    load_stage(0, 0);
    CP_COMMIT();
    load_stage(1, 1);
    CP_COMMIT();

    for (int kt = 0; kt < NKT; kt++) {
        const int cur = kt & 1;
        CP_WAIT(1);
        __syncthreads();

        const uint32_t st = sb + cur * STAGE_B;
#pragma unroll
        for (int kc = 0; kc < 2; kc++) {
            const int kb = kc * 16;
            uint32_t ah[4][4], al[4][4];
#pragma unroll
            for (int mt = 0; mt < 4; mt++) {
                uint32_t off = (uint32_t)((a_row + mt * 16) * STR + kb + a_kof) * 2;
                ldsm_x4(ah[mt][0], ah[mt][1], ah[mt][2], ah[mt][3], st + OAH + off);
                ldsm_x4(al[mt][0], al[mt][1], al[mt][2], al[mt][3], st + OAL + off);
            }
            uint32_t bh[4][2], bl[4][2];
#pragma unroll
            for (int nt = 0; nt < 4; nt++) {
                uint32_t off = (uint32_t)((b_row + nt * 8) * STR + kb + b_kof) * 2;
                ldsm_x2(bh[nt][0], bh[nt][1], st + OBH + off);
                ldsm_x2(bl[nt][0], bl[nt][1], st + OBL + off);
            }
#pragma unroll
            for (int mt = 0; mt < 4; mt++)
#pragma unroll
                for (int nt = 0; nt < 4; nt++) {
                    float* c = acc[mt][nt];
                    mma16816(c, ah[mt][0], ah[mt][1], ah[mt][2], ah[mt][3],
                             bh[nt][0], bh[nt][1]);
                    mma16816(c, ah[mt][0], ah[mt][1], ah[mt][2], ah[mt][3],
                             bl[nt][0], bl[nt][1]);
                    mma16816(c, al[mt][0], al[mt][1], al[mt][2], al[mt][3],
                             bh[nt][0], bh[nt][1]);
                }
        }

        __syncthreads();
        if (kt + 2 < NKT) load_stage(cur, kt + 2);
        CP_COMMIT();
    }

#pragma unroll
    for (int mt = 0; mt < 4; mt++) {
        int rm = m0 + warp_m + mt * 16 + grp;
#pragma unroll
        for (int nt = 0; nt < 4; nt++) {
            int cn = n0 + warp_n + nt * 8 + tig * 2;
            float2 v0, v1;
            v0.x = tanhf(acc[mt][nt][0] * WUNSCALE);
            v0.y = tanhf(acc[mt][nt][1] * WUNSCALE);
            v1.x = tanhf(acc[mt][nt][2] * WUNSCALE);
            v1.y = tanhf(acc[mt][nt][3] * WUNSCALE);
            *(float2*)(g_ic + (size_t)rm * D_ + cn) = v0;
            *(float2*)(g_ic + (size_t)(rm + 8) * D_ + cn) = v1;
        }
    }

    __threadfence();
    __syncthreads();
    if (tid == 0) atomicAdd(&g_done[y >> 3], 1);
}

// ---------------------------------------------------------------------------
// lif item worker: one (batch, seg, chain-block-of-256).
// ---------------------------------------------------------------------------
__device__ void lif_item(int item, const float* __restrict__ noise,
                         float r, float* __restrict__ out, int tid) {
    const int batch = item >> 5;
    const int sub = item & 31;
    const int seg = sub >> 2;
    const int cb = sub & 3;
    const int chain = batch * 1024 + cb * 256 + tid;
    const int d = chain & 1023;
    const size_t base = (size_t)batch * T_ * D_ + d;

    if (tid == 0) {
        while (atomicAdd(&g_done[batch], 0) < 64) __nanosleep(256);
    }
    __syncthreads();
    __threadfence();

    const float* icp = g_ic + base;
    const float* nzp = noise + base;
    const float omr = 1.0f - r;
    const float rh = r * 0.5f;

    float mem = 0.0f;
    const int t0 = seg * SEGLEN;
    const int tw0 = (t0 - WARMUP) > 0 ? (t0 - WARMUP) : 0;

    for (int tc = tw0; tc < t0; tc += 16) {
        float icv[16], nzv[16];
#pragma unroll
        for (int u = 0; u < 16; u++) {
            size_t idx = (size_t)(tc + u) * D_;
            icv[u] = icp[idx];
            nzv[u] = nzp[idx];
        }
#pragma unroll
        for (int u = 0; u < 16; u++) {
            bool s;
            mem = lif_step(mem, icv[u], nzv[u], s);
        }
    }

    for (int tc = t0; tc < t0 + SEGLEN; tc += 16) {
        float icv[16], nzv[16], xtv[16];
#pragma unroll
        for (int u = 0; u < 16; u++) {
            size_t idx = (size_t)(tc + u) * D_;
            icv[u] = icp[idx];
            nzv[u] = nzp[idx];
            xtv[u] = __half2float(g_xh[base + idx]);
        }
        unsigned smask = 0;
#pragma unroll
        for (int u = 0; u < 16; u++) {
            bool s;
            mem = lif_step(mem, icv[u], nzv[u], s);
            smask |= ((unsigned)s) << u;
        }
#pragma unroll
        for (int u = 0; u < 16; u++) {
            float sv = (float)((smask >> u) & 1u);
            float o = tanhf((rh * sv * icv[u] + omr * xtv[u]) * 0.5f);
            out[base + (size_t)(tc + u) * D_] = o;
        }
    }
}

// ---------------------------------------------------------------------------
// Persistent mega-kernel: one queue, 4 phases (W-prep, X-prep, GEMM, LIF).
// Deadlock-free: phase p work claimed only after phases <p fully claimed;
// claimed work executes on resident CTAs, so flag spins always progress.
// ---------------------------------------------------------------------------
__global__ __launch_bounds__(256, 2)
void mega_kernel(const float* __restrict__ x,
                 const float* __restrict__ W,
                 const float* __restrict__ noise,
                 const float* __restrict__ rs,
                 float* __restrict__ out) {
    extern __shared__ __align__(128) char dsm[];
    const int tid = threadIdx.x;
    __shared__ int s_work;

    const float r = 1.0f / (1.0f + expf(-rs[0]));

    for (;;) {
        if (tid == 0) s_work = atomicAdd(&g_q, 1);
        __syncthreads();
        int q = s_work;
        __syncthreads();
        if (q >= QEND) break;
        if (q < QX0) {
            w_item(q - QW0, W, tid);
        } else if (q < QG0) {
            x_item(q - QX0, x, tid);
        } else if (q < QL0) {
            gemm_tile(q - QG0, dsm, tid);
        } else {
            lif_item(q - QL0, noise, r, out, tid);
        }
    }
}

// ---------------------------------------------------------------------------
extern "C" void kernel_launch(void* const* d_in, const int* in_sizes, int n_in,
                              void* d_out, int out_size) {
    (void)out_size;
    const float* x = nullptr;
    const float* W = nullptr;
    const float* rs = nullptr;
    const float* nz = nullptr;
    for (int i = 0; i < n_in; i++) {
        if (in_sizes[i] == NELEM) {
            if (!x) x = (const float*)d_in[i];
            else nz = (const float*)d_in[i];
        } else if (in_sizes[i] == D_ * D_) {
            W = (const float*)d_in[i];
        } else if (in_sizes[i] == 1) {
            rs = (const float*)d_in[i];
        }
    }

    cudaFuncSetAttribute(mega_kernel,
                         cudaFuncAttributeMaxDynamicSharedMemorySize, 2 * STAGE_B);

    reset_kernel<<<1, 256>>>();
    mega_kernel<<<GRID_PERSIST, 256, 2 * STAGE_B>>>(x, W, nz, rs, (float*)d_out);
}